// round 16
// baseline (speedup 1.0000x reference)
#include <cuda_runtime.h>
#include <math.h>

#define NGR    256
#define NPG_   256
#define FDIM   128
#define EPG    4096
#define DLAT   97
#define SPP    100
#define KTOP   30
#define C1_    16
#define C2_    32
#define T2_    11
#define DENSE_ 352
#define NT     512
#define NW     16

typedef unsigned int   u32;
typedef unsigned short u16;

__device__ float h1g_buf[NGR * NPG_ * 32];   // 8MB

// shared layout (float units) — total 28292 floats = 113168 B (2 CTAs/SM)
#define OFF_A     0
#define OFF_B     8192
#define OFF_C     16416
#define OFF_Z4    24608
#define OFF_INVD  24864
#define OFF_BS    25120
#define OFF_OFFS  25216
#define OFF_CNT   25473
#define OFF_ELIST 25732
#define SM_FLOATS 28292
static const int SMEM_BYTES = SM_FLOATS * 4;

__device__ __forceinline__ float agg4(const float* __restrict__ Bp, uint2 cur, int lane) {
    int i0 = (int)(cur.x & 0xffffu), i1 = (int)(cur.x >> 16);
    int i2 = (int)(cur.y & 0xffffu), i3 = (int)(cur.y >> 16);
    return (Bp[i0 + lane] + Bp[i1 + lane]) + (Bp[i2 + lane] + Bp[i3 + lane]);
}

__global__ __launch_bounds__(NT, 2)
void dgcnn_kernel(const float* __restrict__ nf,
                  const int* __restrict__ src, const int* __restrict__ dst,
                  const int* __restrict__ degs,
                  const float* __restrict__ W0, const float* __restrict__ b0,
                  const float* __restrict__ W1, const float* __restrict__ b1,
                  const float* __restrict__ W2, const float* __restrict__ b2,
                  const float* __restrict__ W3, const float* __restrict__ b3,
                  const float* __restrict__ c1w, const float* __restrict__ c1b,
                  const float* __restrict__ c2w, const float* __restrict__ c2b,
                  const float* __restrict__ ow, const float* __restrict__ ob,
                  float* __restrict__ out)
{
    extern __shared__ float sm[];
    float* A     = sm + OFF_A;
    float* B     = sm + OFF_B;
    float* C     = sm + OFF_C;
    float* z4    = sm + OFF_Z4;
    float* invd  = sm + OFF_INVD;
    float* bs    = sm + OFF_BS;
    int*   offs  = (int*)(sm + OFF_OFFS);
    int*   cnt   = (int*)(sm + OFF_CNT);
    u16*   elist = (u16*)(sm + OFF_ELIST);

    const int b    = blockIdx.x;
    const int t    = threadIdx.x;
    const int w    = t >> 5;
    const int lane = t & 31;
    const int base = b * NPG_;

    // ---- init ----
    int pdeg = 0;
    if (t < 256) {
        int d = degs[base + t];
        pdeg = (d + 3) & ~3;
        invd[t] = 1.0f / ((float)d + 1.0f);
        cnt[t] = d;
    }
    B[256 * 32 + lane] = 0.f;   // dummy row
    for (int i = t; i < FDIM * 32; i += NT) C[i] = W0[i];
    if (t < 32) { bs[t] = b0[t]; bs[32 + t] = b1[t]; bs[64 + t] = b2[t]; }

    // ---- shfl-based scan of padded degrees -> offs (exclusive) ----
    {
        int* wsum = (int*)B;       // B[0..7] transient
        int* wpre = wsum + 8;      // B[8..15]
        int x = 0;
        if (t < 256) {
            x = pdeg;
#pragma unroll
            for (int d = 1; d < 32; d <<= 1) {
                int y = __shfl_up_sync(0xffffffffu, x, d);
                if (lane >= d) x += y;
            }
            if (lane == 31) wsum[w] = x;
        }
        __syncthreads();
        if (w == 0) {
            int v = (lane < 8) ? wsum[lane] : 0;
#pragma unroll
            for (int d = 1; d < 8; d <<= 1) {
                int y = __shfl_up_sync(0xffffffffu, v, d);
                if (lane >= d) v += y;
            }
            if (lane < 8) wpre[lane] = v - wsum[lane];
            if (lane == 7) offs[256] = v;
        }
        __syncthreads();
        if (t < 256) offs[t] = x - pdeg + wpre[w];
        __syncthreads();
    }
    int fill_beg = 0, fill_end = 0;
    if (t < 256) {
        fill_beg = offs[t] + cnt[t];
        fill_end = offs[t + 1];
        cnt[t] = offs[t];
    }
    __syncthreads();

    // ---- build CSR (values ls<<5 as u16) ----
    for (int i = t * 4; i < EPG; i += NT * 4) {
        int4 s4 = *(const int4*)(src + b * EPG + i);
        int4 d4 = *(const int4*)(dst + b * EPG + i);
        int p0 = atomicAdd(&cnt[d4.x - base], 1); elist[p0] = (u16)((s4.x - base) << 5);
        int p1 = atomicAdd(&cnt[d4.y - base], 1); elist[p1] = (u16)((s4.y - base) << 5);
        int p2 = atomicAdd(&cnt[d4.z - base], 1); elist[p2] = (u16)((s4.z - base) << 5);
        int p3 = atomicAdd(&cnt[d4.w - base], 1); elist[p3] = (u16)((s4.w - base) << 5);
    }
    __syncthreads();
    for (int p = fill_beg; p < fill_end; p++) elist[p] = (u16)(256 << 5);
    __syncthreads();

    // ---- Layer 0 GEMM: B = nf @ W0 (8-node groups, MLP=8) ----
    for (int gid = w; gid < 32; gid += NW) {
        int n0 = gid * 8;
        const float* nfb = nf + (size_t)(base + n0) * FDIM;
        float acc[8] = {0.f,0.f,0.f,0.f,0.f,0.f,0.f,0.f};
#pragma unroll 2
        for (int k0 = 0; k0 < FDIM; k0 += 4) {
            float w0v = C[(k0 + 0) * 32 + lane];
            float w1v = C[(k0 + 1) * 32 + lane];
            float w2v = C[(k0 + 2) * 32 + lane];
            float w3v = C[(k0 + 3) * 32 + lane];
#pragma unroll
            for (int i = 0; i < 8; i++) {
                float4 r = __ldg((const float4*)(nfb + i * FDIM + k0));
                acc[i] = fmaf(r.x, w0v, acc[i]);
                acc[i] = fmaf(r.y, w1v, acc[i]);
                acc[i] = fmaf(r.z, w2v, acc[i]);
                acc[i] = fmaf(r.w, w3v, acc[i]);
            }
        }
#pragma unroll
        for (int i = 0; i < 8; i++)
            B[(n0 + i) * 32 + lane] = acc[i];
    }
    __syncthreads();

    // ---- Layer 0 aggregate + tanh -> A (= h1); fused global store ----
    for (int n = w; n < 256; n += NW) {
        float acc = B[n * 32 + lane];
        int beg = offs[n], end = offs[n + 1];
        int j = beg;
        for (; j + 8 <= end; j += 8) {
            uint2 ea = *(const uint2*)(elist + j);
            uint2 eb = *(const uint2*)(elist + j + 4);
            acc += agg4(B, ea, lane) + agg4(B, eb, lane);
        }
        if (j < end) {
            uint2 ea = *(const uint2*)(elist + j);
            acc += agg4(B, ea, lane);
        }
        float h = tanhf((acc + bs[lane]) * invd[n]);
        A[n * 32 + lane] = h;
        h1g_buf[(size_t)(base + n) * 32 + lane] = h;
    }
    __syncthreads();

    // ---- Layers 1,2 (32->32); dual accumulators ----
    {
        float* hin = A;
        for (int L = 0; L < 2; L++) {
            const float* Wg = (L == 0) ? W1 : W2;
            float bv = bs[32 + L * 32 + lane];
            float* hout = (L == 0) ? C : A;   // L1 -> C (h2), L2 -> A (h3)

            float wr[32];
#pragma unroll
            for (int k = 0; k < 32; k++) wr[k] = __ldg(Wg + k * 32 + lane);
            for (int n = w; n < 256; n += NW) {
                const float* row = hin + n * 32;
                float a0 = 0.f, a1 = 0.f;
#pragma unroll
                for (int k = 0; k < 32; k += 4) {
                    float4 r4 = *(const float4*)(row + k);
                    a0 = fmaf(r4.x, wr[k],     a0);
                    a1 = fmaf(r4.y, wr[k + 1], a1);
                    a0 = fmaf(r4.z, wr[k + 2], a0);
                    a1 = fmaf(r4.w, wr[k + 3], a1);
                }
                B[n * 32 + lane] = a0 + a1;
            }
            __syncthreads();

            for (int n = w; n < 256; n += NW) {
                float acc = B[n * 32 + lane];
                int beg = offs[n], end = offs[n + 1];
                int j = beg;
                for (; j + 8 <= end; j += 8) {
                    uint2 ea = *(const uint2*)(elist + j);
                    uint2 eb = *(const uint2*)(elist + j + 4);
                    acc += agg4(B, ea, lane) + agg4(B, eb, lane);
                }
                if (j < end) {
                    uint2 ea = *(const uint2*)(elist + j);
                    acc += agg4(B, ea, lane);
                }
                hout[n * 32 + lane] = tanhf((acc + bv) * invd[n]);
            }
            __syncthreads();
            hin = hout;
        }
    }

    // ---- Layer 3 (32->1) -> z4 ; g1 in B[0..256]; agg split over 512 threads ----
    {
        float* g1 = B;
        float w3r = __ldg(W3 + lane);
        float b3v = __ldg(b3);
        if (t == 0) g1[256] = 0.f;
        for (int n = w; n < 256; n += NW) {
            float v = A[n * 32 + lane] * w3r;   // A = h3
#pragma unroll
            for (int off = 16; off; off >>= 1)
                v += __shfl_xor_sync(0xffffffffu, v, off);
            if (lane == 0) g1[n] = v;
        }
        __syncthreads();
        float* partf = B + 1024;
        {
            int node = t & 255, half = t >> 8;
            int beg = offs[node], end = offs[node + 1];
            int h0 = ((end - beg) >> 2) >> 1;      // 4-groups in first half
            int jb = half ? beg + (h0 << 2) : beg;
            int je = half ? end : beg + (h0 << 2);
            float acc = 0.f;
            for (int j = jb; j < je; j += 4) {
                uint2 ea = *(const uint2*)(elist + j);
                acc += (g1[(ea.x & 0xffffu) >> 5] + g1[(ea.x >> 16) >> 5])
                     + (g1[(ea.y & 0xffffu) >> 5] + g1[(ea.y >> 16) >> 5]);
            }
            partf[t] = acc;
        }
        __syncthreads();
        if (t < 256) {
            float acc = g1[t] + partf[t] + partf[t + 256];
            z4[t] = tanhf((acc + b3v) * invd[t]);
        }
        __syncthreads();
    }

    // ---- sortpool rank selection, split across 512 threads ----
    int* selrow = cnt;
    int* part = (int*)(B + 2048);
    {
        int node = t & 255;
        int half = t >> 8;
        float v = z4[node];
        int r = 0;
        int j0 = half * 128;
#pragma unroll 4
        for (int jj = 0; jj < 128; jj += 4) {
            int j = j0 + jj;
            float4 u4 = *(const float4*)(z4 + j);
            r += (int)((u4.x > v) || (u4.x == v && (j    ) < node));
            r += (int)((u4.y > v) || (u4.y == v && (j + 1) < node));
            r += (int)((u4.z > v) || (u4.z == v && (j + 2) < node));
            r += (int)((u4.w > v) || (u4.w == v && (j + 3) < node));
        }
        part[t] = r;
    }
    __syncthreads();
    if (t < 256) {
        int r = part[t] + part[t + 256];
        if (r < KTOP) selrow[r] = t;
    }
    __syncthreads();

    // ---- gather sp[30][100-padded] ----
    float* sp = B + 512;
    for (int i = t; i < KTOP * DLAT; i += NT) {
        int k = i / DLAT, d = i - k * DLAT;
        int n = selrow[k];
        float v;
        if (d < 32)      v = h1g_buf[(size_t)(base + n) * 32 + d];
        else if (d < 64) v = C[n * 32 + d - 32];
        else if (d < 96) v = A[n * 32 + d - 64];
        else             v = z4[n];
        sp[k * SPP + d] = v;
    }
    __syncthreads();

    // ---- stage conv weights into A ----
    float* c1s = A;
    float* c2s = A + 2000;
    for (int i = t; i < C1_ * DLAT; i += NT) {
        int c = i / DLAT, d = i - c * DLAT;
        c1s[c * SPP + d] = c1w[i];
    }
    for (int i = t; i < C2_ * C1_ * 5; i += NT) c2s[i] = c2w[i];
    __syncthreads();

    // ---- conv1 + relu -> out1[16][30] ----
    float* out1 = B + 3600;
    for (int i = t; i < C1_ * KTOP; i += NT) {
        int c = i & 15, k = i >> 4;
        float acc = c1b[c];
        const float4* wr4 = (const float4*)(c1s + c * SPP);
        const float4* sr4 = (const float4*)(sp + k * SPP);
#pragma unroll 4
        for (int q = 0; q < 24; q++) {
            float4 s4 = sr4[q], w4 = wr4[q];
            acc = fmaf(s4.x, w4.x, acc);
            acc = fmaf(s4.y, w4.y, acc);
            acc = fmaf(s4.z, w4.z, acc);
            acc = fmaf(s4.w, w4.w, acc);
        }
        acc = fmaf(sp[k * SPP + 96], c1s[c * SPP + 96], acc);
        out1[c * KTOP + k] = fmaxf(acc, 0.f);
    }
    __syncthreads();

    // ---- maxpool(2,2) -> pool[16][15] ----
    float* pool = B + 4200;
    if (t < C1_ * 15) {
        int c = t / 15, tt = t - c * 15;
        pool[t] = fmaxf(out1[c * KTOP + 2 * tt], out1[c * KTOP + 2 * tt + 1]);
    }
    __syncthreads();

    // ---- conv2 + relu -> out2[32][11] ----
    float* out2 = B + 4500;
    for (int i = t; i < C2_ * T2_; i += NT) {
        int c2 = i / T2_, tt = i - c2 * T2_;
        float acc = c2b[c2];
#pragma unroll
        for (int c1 = 0; c1 < C1_; c1++) {
            const float* wv = c2s + (c2 * C1_ + c1) * 5;
            const float* pv = pool + c1 * 15 + tt;
#pragma unroll
            for (int j = 0; j < 5; j++) acc = fmaf(pv[j], wv[j], acc);
        }
        out2[i] = fmaxf(acc, 0.f);
    }
    __syncthreads();

    // ---- dense [352]x[352,2] + relu ----
    if (w == 0) {
        float a0 = 0.f, a1 = 0.f;
        for (int i = lane; i < DENSE_; i += 32) {
            float x = out2[i];
            a0 = fmaf(x, ow[i * 2 + 0], a0);
            a1 = fmaf(x, ow[i * 2 + 1], a1);
        }
#pragma unroll
        for (int off = 16; off; off >>= 1) {
            a0 += __shfl_xor_sync(0xffffffffu, a0, off);
            a1 += __shfl_xor_sync(0xffffffffu, a1, off);
        }
        if (lane == 0) {
            out[b * 2 + 0] = fmaxf(a0 + ob[0], 0.f);
            out[b * 2 + 1] = fmaxf(a1 + ob[1], 0.f);
        }
    }
}

extern "C" void kernel_launch(void* const* d_in, const int* in_sizes, int n_in,
                              void* d_out, int out_size)
{
    int iSrc, iDst, iDeg, iW0, ib0, iW1, ib1, iW2, ib2, iW3, ib3;
    int ic1w, ic1b, ic2w, ic2b, iow, iob;
    if (n_in > 1 && in_sizes[1] == NGR * EPG) {
        iSrc = 1; iDst = 2; iDeg = 3;
        iW0 = 4;  ib0 = 5;  iW1 = 6;  ib1 = 7;
        iW2 = 8;  ib2 = 9;  iW3 = 10; ib3 = 11;
        ic1w = 12; ic1b = 13; ic2w = 14; ic2b = 15; iow = 16; iob = 17;
    } else {
        iW0 = 1;  ib0 = 2;  iW1 = 3;  ib1 = 4;
        iW2 = 5;  ib2 = 6;  iW3 = 7;  ib3 = 8;
        ic1w = 9; ic1b = 10; ic2w = 11; ic2b = 12; iow = 13; iob = 14;
        iSrc = 15; iDst = 16; iDeg = 17;
    }

    cudaFuncSetAttribute(dgcnn_kernel,
                         cudaFuncAttributeMaxDynamicSharedMemorySize, SMEM_BYTES);

    dgcnn_kernel<<<NGR, NT, SMEM_BYTES>>>(
        (const float*)d_in[0],
        (const int*)d_in[iSrc], (const int*)d_in[iDst], (const int*)d_in[iDeg],
        (const float*)d_in[iW0], (const float*)d_in[ib0],
        (const float*)d_in[iW1], (const float*)d_in[ib1],
        (const float*)d_in[iW2], (const float*)d_in[ib2],
        (const float*)d_in[iW3], (const float*)d_in[ib3],
        (const float*)d_in[ic1w], (const float*)d_in[ic1b],
        (const float*)d_in[ic2w], (const float*)d_in[ic2b],
        (const float*)d_in[iow], (const float*)d_in[iob],
        (float*)d_out);
}

// round 17
// speedup vs baseline: 1.0869x; 1.0869x over previous
#include <cuda_runtime.h>
#include <math.h>

#define NGR    256
#define NPG_   256
#define FDIM   128
#define EPG    4096
#define DLAT   97
#define SPP    100
#define KTOP   30
#define C1_    16
#define C2_    32
#define T2_    11
#define DENSE_ 352
#define NT     512
#define NW     16

typedef unsigned int   u32;
typedef unsigned short u16;

__device__ float h1g_buf[NGR * NPG_ * 32];   // 8MB

// shared layout (float units) — total 28292 floats = 113168 B (2 CTAs/SM)
#define OFF_A     0
#define OFF_B     8192
#define OFF_C     16416
#define OFF_Z4    24608
#define OFF_INVD  24864
#define OFF_BS    25120
#define OFF_OFFS  25216
#define OFF_CNT   25473
#define OFF_ELIST 25732
#define SM_FLOATS 28292
static const int SMEM_BYTES = SM_FLOATS * 4;

__device__ __forceinline__ float agg4(const float* __restrict__ Bp, uint2 cur, int lane) {
    int i0 = (int)(cur.x & 0xffffu), i1 = (int)(cur.x >> 16);
    int i2 = (int)(cur.y & 0xffffu), i3 = (int)(cur.y >> 16);
    return (Bp[i0 + lane] + Bp[i1 + lane]) + (Bp[i2 + lane] + Bp[i3 + lane]);
}

__global__ __launch_bounds__(NT, 2)
void dgcnn_kernel(const float* __restrict__ nf,
                  const int* __restrict__ src, const int* __restrict__ dst,
                  const int* __restrict__ degs,
                  const float* __restrict__ W0, const float* __restrict__ b0,
                  const float* __restrict__ W1, const float* __restrict__ b1,
                  const float* __restrict__ W2, const float* __restrict__ b2,
                  const float* __restrict__ W3, const float* __restrict__ b3,
                  const float* __restrict__ c1w, const float* __restrict__ c1b,
                  const float* __restrict__ c2w, const float* __restrict__ c2b,
                  const float* __restrict__ ow, const float* __restrict__ ob,
                  float* __restrict__ out)
{
    extern __shared__ float sm[];
    float* A     = sm + OFF_A;
    float* B     = sm + OFF_B;
    float* C     = sm + OFF_C;
    float* z4    = sm + OFF_Z4;
    float* invd  = sm + OFF_INVD;
    float* bs    = sm + OFF_BS;
    int*   offs  = (int*)(sm + OFF_OFFS);
    int*   cnt   = (int*)(sm + OFF_CNT);
    u16*   elist = (u16*)(sm + OFF_ELIST);

    const int b    = blockIdx.x;
    const int t    = threadIdx.x;
    const int w    = t >> 5;
    const int lane = t & 31;
    const int base = b * NPG_;

    // ---- init ----
    int pdeg = 0;
    if (t < 256) {
        int d = degs[base + t];
        pdeg = (d + 3) & ~3;
        invd[t] = 1.0f / ((float)d + 1.0f);
        cnt[t] = d;
    }
    B[256 * 32 + lane] = 0.f;   // dummy row
    for (int i = t; i < FDIM * 32; i += NT) C[i] = W0[i];
    if (t < 32) { bs[t] = b0[t]; bs[32 + t] = b1[t]; bs[64 + t] = b2[t]; }

    // ---- shfl-based scan of padded degrees -> offs (exclusive) ----
    {
        int* wsum = (int*)B;       // B[0..7] transient
        int* wpre = wsum + 8;      // B[8..15]
        int x = 0;
        if (t < 256) {
            x = pdeg;
#pragma unroll
            for (int d = 1; d < 32; d <<= 1) {
                int y = __shfl_up_sync(0xffffffffu, x, d);
                if (lane >= d) x += y;
            }
            if (lane == 31) wsum[w] = x;
        }
        __syncthreads();
        if (w == 0) {
            int v = (lane < 8) ? wsum[lane] : 0;
#pragma unroll
            for (int d = 1; d < 8; d <<= 1) {
                int y = __shfl_up_sync(0xffffffffu, v, d);
                if (lane >= d) v += y;
            }
            if (lane < 8) wpre[lane] = v - wsum[lane];
            if (lane == 7) offs[256] = v;
        }
        __syncthreads();
        if (t < 256) offs[t] = x - pdeg + wpre[w];
        __syncthreads();
    }
    int fill_beg = 0, fill_end = 0;
    if (t < 256) {
        fill_beg = offs[t] + cnt[t];
        fill_end = offs[t + 1];
        cnt[t] = offs[t];
    }
    __syncthreads();

    // ---- build CSR (values ls<<5 as u16) ----
    for (int i = t * 4; i < EPG; i += NT * 4) {
        int4 s4 = *(const int4*)(src + b * EPG + i);
        int4 d4 = *(const int4*)(dst + b * EPG + i);
        int p0 = atomicAdd(&cnt[d4.x - base], 1); elist[p0] = (u16)((s4.x - base) << 5);
        int p1 = atomicAdd(&cnt[d4.y - base], 1); elist[p1] = (u16)((s4.y - base) << 5);
        int p2 = atomicAdd(&cnt[d4.z - base], 1); elist[p2] = (u16)((s4.z - base) << 5);
        int p3 = atomicAdd(&cnt[d4.w - base], 1); elist[p3] = (u16)((s4.w - base) << 5);
    }
    __syncthreads();
    for (int p = fill_beg; p < fill_end; p++) elist[p] = (u16)(256 << 5);
    __syncthreads();

    // ---- Layer 0 GEMM: B = nf @ W0 ----
    // 4 chunks of 64 nodes staged into A (coalesced), compute from smem (LDS 29cyc)
    for (int chunk = 0; chunk < 4; chunk++) {
        const float4* s4 = (const float4*)(nf + (size_t)(base + chunk * 64) * FDIM);
        float4* d4 = (float4*)A;
#pragma unroll
        for (int q = 0; q < 4; q++) d4[t + q * NT] = s4[t + q * NT];
        __syncthreads();

        int n0 = chunk * 64 + w * 4;
        const float* rowb = A + (w * 4) * FDIM;
        float acc[4] = {0.f, 0.f, 0.f, 0.f};
#pragma unroll 2
        for (int k0 = 0; k0 < FDIM; k0 += 4) {
            float w0v = C[(k0 + 0) * 32 + lane];
            float w1v = C[(k0 + 1) * 32 + lane];
            float w2v = C[(k0 + 2) * 32 + lane];
            float w3v = C[(k0 + 3) * 32 + lane];
#pragma unroll
            for (int i = 0; i < 4; i++) {
                float4 r = *(const float4*)(rowb + i * FDIM + k0);
                acc[i] = fmaf(r.x, w0v, acc[i]);
                acc[i] = fmaf(r.y, w1v, acc[i]);
                acc[i] = fmaf(r.z, w2v, acc[i]);
                acc[i] = fmaf(r.w, w3v, acc[i]);
            }
        }
#pragma unroll
        for (int i = 0; i < 4; i++)
            B[(n0 + i) * 32 + lane] = acc[i];
        __syncthreads();
    }

    // ---- Layer 0 aggregate + tanh -> A (= h1); fused global store ----
    for (int n = w; n < 256; n += NW) {
        float acc = B[n * 32 + lane];
        int beg = offs[n], end = offs[n + 1];
        int j = beg;
        for (; j + 8 <= end; j += 8) {
            uint2 ea = *(const uint2*)(elist + j);
            uint2 eb = *(const uint2*)(elist + j + 4);
            acc += agg4(B, ea, lane) + agg4(B, eb, lane);
        }
        if (j < end) {
            uint2 ea = *(const uint2*)(elist + j);
            acc += agg4(B, ea, lane);
        }
        float h = tanhf((acc + bs[lane]) * invd[n]);
        A[n * 32 + lane] = h;
        h1g_buf[(size_t)(base + n) * 32 + lane] = h;
    }
    __syncthreads();

    // ---- Layers 1,2 (32->32); dual accumulators ----
    {
        float* hin = A;
        for (int L = 0; L < 2; L++) {
            const float* Wg = (L == 0) ? W1 : W2;
            float bv = bs[32 + L * 32 + lane];
            float* hout = (L == 0) ? C : A;   // L1 -> C (h2), L2 -> A (h3)

            float wr[32];
#pragma unroll
            for (int k = 0; k < 32; k++) wr[k] = __ldg(Wg + k * 32 + lane);
            for (int n = w; n < 256; n += NW) {
                const float* row = hin + n * 32;
                float a0 = 0.f, a1 = 0.f;
#pragma unroll
                for (int k = 0; k < 32; k += 4) {
                    float4 r4 = *(const float4*)(row + k);
                    a0 = fmaf(r4.x, wr[k],     a0);
                    a1 = fmaf(r4.y, wr[k + 1], a1);
                    a0 = fmaf(r4.z, wr[k + 2], a0);
                    a1 = fmaf(r4.w, wr[k + 3], a1);
                }
                B[n * 32 + lane] = a0 + a1;
            }
            __syncthreads();

            for (int n = w; n < 256; n += NW) {
                float acc = B[n * 32 + lane];
                int beg = offs[n], end = offs[n + 1];
                int j = beg;
                for (; j + 8 <= end; j += 8) {
                    uint2 ea = *(const uint2*)(elist + j);
                    uint2 eb = *(const uint2*)(elist + j + 4);
                    acc += agg4(B, ea, lane) + agg4(B, eb, lane);
                }
                if (j < end) {
                    uint2 ea = *(const uint2*)(elist + j);
                    acc += agg4(B, ea, lane);
                }
                hout[n * 32 + lane] = tanhf((acc + bv) * invd[n]);
            }
            __syncthreads();
            hin = hout;
        }
    }

    // ---- Layer 3 (32->1) -> z4 ; g1 in B[0..256]; agg split over 512 threads ----
    {
        float* g1 = B;
        float w3r = __ldg(W3 + lane);
        float b3v = __ldg(b3);
        if (t == 0) g1[256] = 0.f;
        for (int n = w; n < 256; n += NW) {
            float v = A[n * 32 + lane] * w3r;   // A = h3
#pragma unroll
            for (int off = 16; off; off >>= 1)
                v += __shfl_xor_sync(0xffffffffu, v, off);
            if (lane == 0) g1[n] = v;
        }
        __syncthreads();
        float* partf = B + 1024;
        {
            int node = t & 255, half = t >> 8;
            int beg = offs[node], end = offs[node + 1];
            int h0 = ((end - beg) >> 2) >> 1;
            int jb = half ? beg + (h0 << 2) : beg;
            int je = half ? end : beg + (h0 << 2);
            float acc = 0.f;
            for (int j = jb; j < je; j += 4) {
                uint2 ea = *(const uint2*)(elist + j);
                acc += (g1[(ea.x & 0xffffu) >> 5] + g1[(ea.x >> 16) >> 5])
                     + (g1[(ea.y & 0xffffu) >> 5] + g1[(ea.y >> 16) >> 5]);
            }
            partf[t] = acc;
        }
        __syncthreads();
        if (t < 256) {
            float acc = g1[t] + partf[t] + partf[t + 256];
            z4[t] = tanhf((acc + b3v) * invd[t]);
        }
        __syncthreads();
    }

    // ---- sortpool rank selection, split across 512 threads ----
    int* selrow = cnt;
    int* part = (int*)(B + 2048);
    {
        int node = t & 255;
        int half = t >> 8;
        float v = z4[node];
        int r = 0;
        int j0 = half * 128;
#pragma unroll 4
        for (int jj = 0; jj < 128; jj += 4) {
            int j = j0 + jj;
            float4 u4 = *(const float4*)(z4 + j);
            r += (int)((u4.x > v) || (u4.x == v && (j    ) < node));
            r += (int)((u4.y > v) || (u4.y == v && (j + 1) < node));
            r += (int)((u4.z > v) || (u4.z == v && (j + 2) < node));
            r += (int)((u4.w > v) || (u4.w == v && (j + 3) < node));
        }
        part[t] = r;
    }
    __syncthreads();
    if (t < 256) {
        int r = part[t] + part[t + 256];
        if (r < KTOP) selrow[r] = t;
    }
    __syncthreads();

    // ---- gather sp[30][100-padded] ----
    float* sp = B + 512;
    for (int i = t; i < KTOP * DLAT; i += NT) {
        int k = i / DLAT, d = i - k * DLAT;
        int n = selrow[k];
        float v;
        if (d < 32)      v = h1g_buf[(size_t)(base + n) * 32 + d];
        else if (d < 64) v = C[n * 32 + d - 32];
        else if (d < 96) v = A[n * 32 + d - 64];
        else             v = z4[n];
        sp[k * SPP + d] = v;
    }
    __syncthreads();

    // ---- stage conv weights into A ----
    float* c1s = A;
    float* c2s = A + 2000;
    for (int i = t; i < C1_ * DLAT; i += NT) {
        int c = i / DLAT, d = i - c * DLAT;
        c1s[c * SPP + d] = c1w[i];
    }
    for (int i = t; i < C2_ * C1_ * 5; i += NT) c2s[i] = c2w[i];
    __syncthreads();

    // ---- conv1 + relu -> out1[16][30] ----
    float* out1 = B + 3600;
    for (int i = t; i < C1_ * KTOP; i += NT) {
        int c = i & 15, k = i >> 4;
        float acc = c1b[c];
        const float4* wr4 = (const float4*)(c1s + c * SPP);
        const float4* sr4 = (const float4*)(sp + k * SPP);
#pragma unroll 4
        for (int q = 0; q < 24; q++) {
            float4 s4 = sr4[q], w4 = wr4[q];
            acc = fmaf(s4.x, w4.x, acc);
            acc = fmaf(s4.y, w4.y, acc);
            acc = fmaf(s4.z, w4.z, acc);
            acc = fmaf(s4.w, w4.w, acc);
        }
        acc = fmaf(sp[k * SPP + 96], c1s[c * SPP + 96], acc);
        out1[c * KTOP + k] = fmaxf(acc, 0.f);
    }
    __syncthreads();

    // ---- maxpool(2,2) -> pool[16][15] ----
    float* pool = B + 4200;
    if (t < C1_ * 15) {
        int c = t / 15, tt = t - c * 15;
        pool[t] = fmaxf(out1[c * KTOP + 2 * tt], out1[c * KTOP + 2 * tt + 1]);
    }
    __syncthreads();

    // ---- conv2 + relu -> out2[32][11] ----
    float* out2 = B + 4500;
    for (int i = t; i < C2_ * T2_; i += NT) {
        int c2 = i / T2_, tt = i - c2 * T2_;
        float acc = c2b[c2];
#pragma unroll
        for (int c1 = 0; c1 < C1_; c1++) {
            const float* wv = c2s + (c2 * C1_ + c1) * 5;
            const float* pv = pool + c1 * 15 + tt;
#pragma unroll
            for (int j = 0; j < 5; j++) acc = fmaf(pv[j], wv[j], acc);
        }
        out2[i] = fmaxf(acc, 0.f);
    }
    __syncthreads();

    // ---- dense [352]x[352,2] + relu ----
    if (w == 0) {
        float a0 = 0.f, a1 = 0.f;
        for (int i = lane; i < DENSE_; i += 32) {
            float x = out2[i];
            a0 = fmaf(x, ow[i * 2 + 0], a0);
            a1 = fmaf(x, ow[i * 2 + 1], a1);
        }
#pragma unroll
        for (int off = 16; off; off >>= 1) {
            a0 += __shfl_xor_sync(0xffffffffu, a0, off);
            a1 += __shfl_xor_sync(0xffffffffu, a1, off);
        }
        if (lane == 0) {
            out[b * 2 + 0] = fmaxf(a0 + ob[0], 0.f);
            out[b * 2 + 1] = fmaxf(a1 + ob[1], 0.f);
        }
    }
}

extern "C" void kernel_launch(void* const* d_in, const int* in_sizes, int n_in,
                              void* d_out, int out_size)
{
    int iSrc, iDst, iDeg, iW0, ib0, iW1, ib1, iW2, ib2, iW3, ib3;
    int ic1w, ic1b, ic2w, ic2b, iow, iob;
    if (n_in > 1 && in_sizes[1] == NGR * EPG) {
        iSrc = 1; iDst = 2; iDeg = 3;
        iW0 = 4;  ib0 = 5;  iW1 = 6;  ib1 = 7;
        iW2 = 8;  ib2 = 9;  iW3 = 10; ib3 = 11;
        ic1w = 12; ic1b = 13; ic2w = 14; ic2b = 15; iow = 16; iob = 17;
    } else {
        iW0 = 1;  ib0 = 2;  iW1 = 3;  ib1 = 4;
        iW2 = 5;  ib2 = 6;  iW3 = 7;  ib3 = 8;
        ic1w = 9; ic1b = 10; ic2w = 11; ic2b = 12; iow = 13; iob = 14;
        iSrc = 15; iDst = 16; iDeg = 17;
    }

    cudaFuncSetAttribute(dgcnn_kernel,
                         cudaFuncAttributeMaxDynamicSharedMemorySize, SMEM_BYTES);

    dgcnn_kernel<<<NGR, NT, SMEM_BYTES>>>(
        (const float*)d_in[0],
        (const int*)d_in[iSrc], (const int*)d_in[iDst], (const int*)d_in[iDeg],
        (const float*)d_in[iW0], (const float*)d_in[ib0],
        (const float*)d_in[iW1], (const float*)d_in[ib1],
        (const float*)d_in[iW2], (const float*)d_in[ib2],
        (const float*)d_in[iW3], (const float*)d_in[ib3],
        (const float*)d_in[ic1w], (const float*)d_in[ic1b],
        (const float*)d_in[ic2w], (const float*)d_in[ic2b],
        (const float*)d_in[iow], (const float*)d_in[iob],
        (float*)d_out);
}